// round 4
// baseline (speedup 1.0000x reference)
#include <cuda_runtime.h>
#include <cstdint>

#define B_   16
#define NQ_  2304
#define D_   512
#define NH_  8
#define DK_  64
#define NK_  256
#define EPS_ 1e-5f

// ---------------- scratch (device globals; no allocation allowed) ----------------
__device__ float g_qp[(size_t)B_ * NQ_ * D_];   // Q projection (b,q, h*64+d)
__device__ float g_x [(size_t)B_ * NK_ * D_];   // conv+LN output (b,n,c)
__device__ float g_kp[(size_t)B_ * NK_ * D_];   // K projection (b,n, h*64+d)
__device__ float g_vp[(size_t)B_ * NK_ * D_];   // V projection (b,n, h*64+d)
__device__ float g_U [(size_t)B_ * NQ_ * D_];   // P@V (raw, pre-norm)
__device__ float g_vcol[B_ * NH_ * DK_];        // per-(b,h) column sums of V
__device__ float g_ssq [B_ * NH_];              // per-(b,h) sum of (P - 1/256)^2
__device__ float g_obias[B_ * D_];              // per-batch corrected output bias

// ---------------- SGEMM: C[M,512] = A[M,512] @ W[512,512] + bias ----------------
// BM=128, BN=128, BK=16, 256 threads, 8x8 per thread, register-staged
// ping-pong smem pipeline (1 barrier per k-step). M multiple of 128.
__global__ __launch_bounds__(256) void sgemm_bias(const float* __restrict__ A,
                                                  const float* __restrict__ W,
                                                  const float* __restrict__ bias,
                                                  float* __restrict__ C)
{
    __shared__ float As[2][16][132];   // [buf][kk][m], padded
    __shared__ float Bs[2][16][132];   // [buf][kk][n], padded
    const int tid = threadIdx.x;
    const int tx  = tid & 15;          // n group (8 cols each)
    const int ty  = tid >> 4;          // m group (8 rows each)
    const int bm  = blockIdx.y * 128;
    const int bn  = blockIdx.x * 128;

    const int am0 = tid >> 2,          akg = tid & 3;
    const int am1 = (tid + 256) >> 2;
    const int bkk0 = tid >> 5,         bng = tid & 31;
    const int bkk1 = (tid + 256) >> 5;

    float acc[8][8];
#pragma unroll
    for (int i = 0; i < 8; i++)
#pragma unroll
        for (int j = 0; j < 8; j++) acc[i][j] = 0.f;

    {
        float4 av0 = *(const float4*)&A[(size_t)(bm + am0) * 512 + akg * 4];
        float4 av1 = *(const float4*)&A[(size_t)(bm + am1) * 512 + akg * 4];
        float4 bv0 = *(const float4*)&W[(size_t)bkk0 * 512 + bn + bng * 4];
        float4 bv1 = *(const float4*)&W[(size_t)bkk1 * 512 + bn + bng * 4];
        As[0][akg * 4 + 0][am0] = av0.x; As[0][akg * 4 + 1][am0] = av0.y;
        As[0][akg * 4 + 2][am0] = av0.z; As[0][akg * 4 + 3][am0] = av0.w;
        As[0][akg * 4 + 0][am1] = av1.x; As[0][akg * 4 + 1][am1] = av1.y;
        As[0][akg * 4 + 2][am1] = av1.z; As[0][akg * 4 + 3][am1] = av1.w;
        *(float4*)&Bs[0][bkk0][bng * 4] = bv0;
        *(float4*)&Bs[0][bkk1][bng * 4] = bv1;
    }
    __syncthreads();

    int buf = 0;
    for (int k0 = 0; k0 < 512; k0 += 16) {
        const bool has_next = (k0 + 16) < 512;
        float4 av0, av1, bv0, bv1;
        if (has_next) {
            const int kn = k0 + 16;
            av0 = *(const float4*)&A[(size_t)(bm + am0) * 512 + kn + akg * 4];
            av1 = *(const float4*)&A[(size_t)(bm + am1) * 512 + kn + akg * 4];
            bv0 = *(const float4*)&W[(size_t)(kn + bkk0) * 512 + bn + bng * 4];
            bv1 = *(const float4*)&W[(size_t)(kn + bkk1) * 512 + bn + bng * 4];
        }
#pragma unroll
        for (int kk = 0; kk < 16; kk++) {
            float a[8], bb[8];
            *(float4*)&a[0]  = *(const float4*)&As[buf][kk][ty * 8];
            *(float4*)&a[4]  = *(const float4*)&As[buf][kk][ty * 8 + 4];
            *(float4*)&bb[0] = *(const float4*)&Bs[buf][kk][tx * 8];
            *(float4*)&bb[4] = *(const float4*)&Bs[buf][kk][tx * 8 + 4];
#pragma unroll
            for (int i = 0; i < 8; i++)
#pragma unroll
                for (int j = 0; j < 8; j++)
                    acc[i][j] = fmaf(a[i], bb[j], acc[i][j]);
        }
        if (has_next) {
            const int nb = buf ^ 1;
            As[nb][akg * 4 + 0][am0] = av0.x; As[nb][akg * 4 + 1][am0] = av0.y;
            As[nb][akg * 4 + 2][am0] = av0.z; As[nb][akg * 4 + 3][am0] = av0.w;
            As[nb][akg * 4 + 0][am1] = av1.x; As[nb][akg * 4 + 1][am1] = av1.y;
            As[nb][akg * 4 + 2][am1] = av1.z; As[nb][akg * 4 + 3][am1] = av1.w;
            *(float4*)&Bs[nb][bkk0][bng * 4] = bv0;
            *(float4*)&Bs[nb][bkk1][bng * 4] = bv1;
        }
        __syncthreads();
        buf ^= 1;
    }

    float bv[8];
    *(float4*)&bv[0] = *(const float4*)&bias[bn + tx * 8];
    *(float4*)&bv[4] = *(const float4*)&bias[bn + tx * 8 + 4];
#pragma unroll
    for (int i = 0; i < 8; i++) {
        float4 o0, o1;
        o0.x = acc[i][0] + bv[0]; o0.y = acc[i][1] + bv[1];
        o0.z = acc[i][2] + bv[2]; o0.w = acc[i][3] + bv[3];
        o1.x = acc[i][4] + bv[4]; o1.y = acc[i][5] + bv[5];
        o1.z = acc[i][6] + bv[6]; o1.w = acc[i][7] + bv[7];
        float* cr = &C[(size_t)(bm + ty * 8 + i) * 512 + bn + tx * 8];
        *(float4*)cr       = o0;
        *(float4*)(cr + 4) = o1;
    }
}

// ---------------- O-proj SGEMM with fused instance-norm scale + per-batch bias ----------
// Same tiling as sgemm_bias, but A-tile elements are scaled by rs[b, k>>6]
// at smem-store time, and the epilogue bias comes from g_obias[b*512 + n].
__global__ __launch_bounds__(256) void sgemm_o_fused(const float* __restrict__ A,
                                                     const float* __restrict__ W,
                                                     float* __restrict__ C)
{
    __shared__ float As[2][16][132];
    __shared__ float Bs[2][16][132];
    __shared__ float rssh[8];
    const int tid = threadIdx.x;
    const int tx  = tid & 15;
    const int ty  = tid >> 4;
    const int bm  = blockIdx.y * 128;
    const int bn  = blockIdx.x * 128;
    const int b   = bm / NQ_;          // tiles never straddle batches (2304 = 18*128)

    const int am0 = tid >> 2,          akg = tid & 3;
    const int am1 = (tid + 256) >> 2;
    const int bkk0 = tid >> 5,         bng = tid & 31;
    const int bkk1 = (tid + 256) >> 5;

    if (tid < 8)
        rssh[tid] = rsqrtf(g_ssq[b * NH_ + tid] * (1.f / ((float)NQ_ * (float)NK_)) + EPS_);
    __syncthreads();

    float acc[8][8];
#pragma unroll
    for (int i = 0; i < 8; i++)
#pragma unroll
        for (int j = 0; j < 8; j++) acc[i][j] = 0.f;

    {
        const float s = rssh[(akg * 4) >> 6];   // k0 = 0
        float4 av0 = *(const float4*)&A[(size_t)(bm + am0) * 512 + akg * 4];
        float4 av1 = *(const float4*)&A[(size_t)(bm + am1) * 512 + akg * 4];
        float4 bv0 = *(const float4*)&W[(size_t)bkk0 * 512 + bn + bng * 4];
        float4 bv1 = *(const float4*)&W[(size_t)bkk1 * 512 + bn + bng * 4];
        As[0][akg * 4 + 0][am0] = av0.x * s; As[0][akg * 4 + 1][am0] = av0.y * s;
        As[0][akg * 4 + 2][am0] = av0.z * s; As[0][akg * 4 + 3][am0] = av0.w * s;
        As[0][akg * 4 + 0][am1] = av1.x * s; As[0][akg * 4 + 1][am1] = av1.y * s;
        As[0][akg * 4 + 2][am1] = av1.z * s; As[0][akg * 4 + 3][am1] = av1.w * s;
        *(float4*)&Bs[0][bkk0][bng * 4] = bv0;
        *(float4*)&Bs[0][bkk1][bng * 4] = bv1;
    }
    __syncthreads();

    int buf = 0;
    for (int k0 = 0; k0 < 512; k0 += 16) {
        const bool has_next = (k0 + 16) < 512;
        float4 av0, av1, bv0, bv1;
        float  sn = 0.f;
        if (has_next) {
            const int kn = k0 + 16;
            sn  = rssh[(kn + akg * 4) >> 6];   // 4-k group never crosses a 64-boundary
            av0 = *(const float4*)&A[(size_t)(bm + am0) * 512 + kn + akg * 4];
            av1 = *(const float4*)&A[(size_t)(bm + am1) * 512 + kn + akg * 4];
            bv0 = *(const float4*)&W[(size_t)(kn + bkk0) * 512 + bn + bng * 4];
            bv1 = *(const float4*)&W[(size_t)(kn + bkk1) * 512 + bn + bng * 4];
        }
#pragma unroll
        for (int kk = 0; kk < 16; kk++) {
            float a[8], bb[8];
            *(float4*)&a[0]  = *(const float4*)&As[buf][kk][ty * 8];
            *(float4*)&a[4]  = *(const float4*)&As[buf][kk][ty * 8 + 4];
            *(float4*)&bb[0] = *(const float4*)&Bs[buf][kk][tx * 8];
            *(float4*)&bb[4] = *(const float4*)&Bs[buf][kk][tx * 8 + 4];
#pragma unroll
            for (int i = 0; i < 8; i++)
#pragma unroll
                for (int j = 0; j < 8; j++)
                    acc[i][j] = fmaf(a[i], bb[j], acc[i][j]);
        }
        if (has_next) {
            const int nb = buf ^ 1;
            As[nb][akg * 4 + 0][am0] = av0.x * sn; As[nb][akg * 4 + 1][am0] = av0.y * sn;
            As[nb][akg * 4 + 2][am0] = av0.z * sn; As[nb][akg * 4 + 3][am0] = av0.w * sn;
            As[nb][akg * 4 + 0][am1] = av1.x * sn; As[nb][akg * 4 + 1][am1] = av1.y * sn;
            As[nb][akg * 4 + 2][am1] = av1.z * sn; As[nb][akg * 4 + 3][am1] = av1.w * sn;
            *(float4*)&Bs[nb][bkk0][bng * 4] = bv0;
            *(float4*)&Bs[nb][bkk1][bng * 4] = bv1;
        }
        __syncthreads();
        buf ^= 1;
    }

    float bv[8];
    *(float4*)&bv[0] = *(const float4*)&g_obias[b * D_ + bn + tx * 8];
    *(float4*)&bv[4] = *(const float4*)&g_obias[b * D_ + bn + tx * 8 + 4];
#pragma unroll
    for (int i = 0; i < 8; i++) {
        float4 o0, o1;
        o0.x = acc[i][0] + bv[0]; o0.y = acc[i][1] + bv[1];
        o0.z = acc[i][2] + bv[2]; o0.w = acc[i][3] + bv[3];
        o1.x = acc[i][4] + bv[4]; o1.y = acc[i][5] + bv[5];
        o1.z = acc[i][6] + bv[6]; o1.w = acc[i][7] + bv[7];
        float* cr = &C[(size_t)(bm + ty * 8 + i) * 512 + bn + tx * 8];
        *(float4*)cr       = o0;
        *(float4*)(cr + 4) = o1;
    }
}

// ---------------- per-batch corrected output bias ----------------
// obias[b,n] = bo[n] - (1/256) * sum_c vcol[b,c] * rs[b, c>>6] * Wo[c,n]
// grid = B_, block = 512 (one thread per n)
__global__ __launch_bounds__(512) void obias_kernel(const float* __restrict__ Wo,
                                                    const float* __restrict__ bo)
{
    __shared__ float sv[512];
    const int b = blockIdx.x;
    const int n = threadIdx.x;
    {
        const int c = n;
        const float rs = rsqrtf(g_ssq[b * NH_ + (c >> 6)] *
                                (1.f / ((float)NQ_ * (float)NK_)) + EPS_);
        sv[c] = g_vcol[b * D_ + c] * rs * (1.f / 256.f);
    }
    __syncthreads();
    float acc = bo[n];
    for (int c = 0; c < 512; c++)
        acc -= sv[c] * Wo[(size_t)c * 512 + n];
    g_obias[b * D_ + n] = acc;
}

// ---------------- depthwise 4x4 stride-3 pad-1 conv + LayerNorm(channel) ----------------
__global__ __launch_bounds__(512) void conv_ln_kernel(const float* __restrict__ q,
                                                      const float* __restrict__ srw,
                                                      const float* __restrict__ srb,
                                                      const float* __restrict__ lng,
                                                      const float* __restrict__ lnb)
{
    const int b   = blockIdx.x >> 8;
    const int pix = blockIdx.x & 255;
    const int oh  = pix >> 4, ow = pix & 15;
    const int c   = threadIdx.x;

    float acc = srb[c];
#pragma unroll
    for (int kh = 0; kh < 4; kh++) {
        int ih = oh * 3 - 1 + kh;
        if (ih < 0 || ih >= 48) continue;
#pragma unroll
        for (int kw = 0; kw < 4; kw++) {
            int iw = ow * 3 - 1 + kw;
            if (iw < 0 || iw >= 48) continue;
            acc = fmaf(q[((size_t)b * NQ_ + ih * 48 + iw) * D_ + c],
                       srw[c * 16 + kh * 4 + kw], acc);
        }
    }
    __shared__ float wred[16];
    __shared__ float stat;
    const int lane = c & 31, wid = c >> 5;

    float s = acc;
#pragma unroll
    for (int off = 16; off; off >>= 1) s += __shfl_xor_sync(0xffffffffu, s, off);
    if (lane == 0) wred[wid] = s;
    __syncthreads();
    if (c == 0) {
        float t = 0.f;
#pragma unroll
        for (int i = 0; i < 16; i++) t += wred[i];
        stat = t * (1.f / 512.f);
    }
    __syncthreads();
    const float mu = stat;
    const float dv = acc - mu;
    float s2 = dv * dv;
#pragma unroll
    for (int off = 16; off; off >>= 1) s2 += __shfl_xor_sync(0xffffffffu, s2, off);
    __syncthreads();
    if (lane == 0) wred[wid] = s2;
    __syncthreads();
    if (c == 0) {
        float t = 0.f;
#pragma unroll
        for (int i = 0; i < 16; i++) t += wred[i];
        stat = t * (1.f / 512.f);
    }
    __syncthreads();
    const float var = stat;
    g_x[((size_t)b * NK_ + pix) * D_ + c] = dv * rsqrtf(var + EPS_) * lng[c] + lnb[c];
}

// ---------------- V column sums + clear ssq ----------------
__global__ void vcol_kernel()
{
    const int bh = blockIdx.x;
    const int b = bh >> 3, h = bh & 7;
    const int d = threadIdx.x;
    float s = 0.f;
    for (int n = 0; n < NK_; n++)
        s += g_vp[((size_t)b * NK_ + n) * D_ + h * DK_ + d];
    g_vcol[b * D_ + h * DK_ + d] = s;
    if (d == 0) g_ssq[bh] = 0.f;
}

// ---------------- fused attention: scores -> head-mix -> softmax -> ssq -> U = P@V ----------
__global__ __launch_bounds__(256, 1) void attn_kernel(const float* __restrict__ tw,
                                                      const float* __restrict__ tb)
{
    extern __shared__ float sm[];
    float* qsh  = sm;                 // 16*64
    float* kvsh = sm + 1024;          // max(64*257, 256*68)
    float* psh  = sm + 1024 + 17408;  // 16*257
    __shared__ float twsh[64];
    __shared__ float tbsh[8];
    __shared__ float ssb[8];

    const int tid  = threadIdx.x;
    const int w    = tid >> 5;
    const int lane = tid & 31;
    const int b    = blockIdx.y;
    const int q0   = blockIdx.x * 16;

    if (tid < 64) twsh[tid] = tw[tid];
    if (tid < 8) { tbsh[tid] = tb[tid]; ssb[tid] = 0.f; }

    float macc[8][2][8];
#pragma unroll
    for (int o = 0; o < 8; o++)
#pragma unroll
        for (int qq = 0; qq < 2; qq++)
#pragma unroll
            for (int kk = 0; kk < 8; kk++) macc[o][qq][kk] = 0.f;

    for (int i = 0; i < 8; i++) {
        {
            int j = tid;
            int r = j >> 4, d4 = (j & 15) * 4;
            *(float4*)&qsh[r * 64 + d4] =
                *(const float4*)&g_qp[((size_t)(b * NQ_ + q0 + r)) * D_ + i * DK_ + d4];
        }
        for (int j = tid; j < 4096; j += 256) {
            int k = j >> 4, d4 = (j & 15) * 4;
            const float4 kv = *(const float4*)&g_kp[((size_t)(b * NK_ + k)) * D_ + i * DK_ + d4];
            kvsh[(d4 + 0) * 257 + k] = kv.x;
            kvsh[(d4 + 1) * 257 + k] = kv.y;
            kvsh[(d4 + 2) * 257 + k] = kv.z;
            kvsh[(d4 + 3) * 257 + k] = kv.w;
        }
        __syncthreads();

        float sacc[2][8];
#pragma unroll
        for (int qq = 0; qq < 2; qq++)
#pragma unroll
            for (int kk = 0; kk < 8; kk++) sacc[qq][kk] = 0.f;

#pragma unroll 8
        for (int d = 0; d < 64; d++) {
            const float q0v = qsh[(2 * w) * 64 + d];
            const float q1v = qsh[(2 * w + 1) * 64 + d];
            const float* kr = &kvsh[d * 257 + lane];
#pragma unroll
            for (int kk = 0; kk < 8; kk++) {
                const float kv = kr[kk * 32];
                sacc[0][kk] = fmaf(q0v, kv, sacc[0][kk]);
                sacc[1][kk] = fmaf(q1v, kv, sacc[1][kk]);
            }
        }
#pragma unroll
        for (int o = 0; o < 8; o++) {
            const float wv = twsh[o * 8 + i] * 0.125f;
#pragma unroll
            for (int qq = 0; qq < 2; qq++)
#pragma unroll
                for (int kk = 0; kk < 8; kk++)
                    macc[o][qq][kk] = fmaf(wv, sacc[qq][kk], macc[o][qq][kk]);
        }
        __syncthreads();
    }

#pragma unroll
    for (int o = 0; o < 8; o++) {
        float ssq_o = 0.f;
        const float bias = tbsh[o];
#pragma unroll
        for (int qq = 0; qq < 2; qq++) {
            float mx = -1e30f;
#pragma unroll
            for (int kk = 0; kk < 8; kk++) {
                macc[o][qq][kk] += bias;
                mx = fmaxf(mx, macc[o][qq][kk]);
            }
#pragma unroll
            for (int off = 16; off; off >>= 1)
                mx = fmaxf(mx, __shfl_xor_sync(0xffffffffu, mx, off));
            float s = 0.f;
#pragma unroll
            for (int kk = 0; kk < 8; kk++) {
                float e = expf(macc[o][qq][kk] - mx);
                macc[o][qq][kk] = e;
                s += e;
            }
#pragma unroll
            for (int off = 16; off; off >>= 1)
                s += __shfl_xor_sync(0xffffffffu, s, off);
            const float inv = 1.f / s;
#pragma unroll
            for (int kk = 0; kk < 8; kk++) {
                const float p = macc[o][qq][kk] * inv;
                macc[o][qq][kk] = p;
                const float d = p - (1.f / 256.f);
                ssq_o = fmaf(d, d, ssq_o);
            }
        }
#pragma unroll
        for (int off = 16; off; off >>= 1)
            ssq_o += __shfl_xor_sync(0xffffffffu, ssq_o, off);
        if (lane == 0) atomicAdd(&ssb[o], ssq_o);
    }

    const int qh = w & 1, dq = w >> 1;
    const int ql = lane >> 2, dl = lane & 3;
    const int qrow = qh * 8 + ql;
    const int dd4  = dq * 16 + dl * 4;

#pragma unroll
    for (int o = 0; o < 8; o++) {
        __syncthreads();
#pragma unroll
        for (int qq = 0; qq < 2; qq++)
#pragma unroll
            for (int kk = 0; kk < 8; kk++)
                psh[(2 * w + qq) * 257 + lane + 32 * kk] = macc[o][qq][kk];
        for (int j = tid; j < 4096; j += 256) {
            int k = j >> 4, d4 = (j & 15) * 4;
            *(float4*)&kvsh[k * 68 + d4] =
                *(const float4*)&g_vp[((size_t)(b * NK_ + k)) * D_ + o * DK_ + d4];
        }
        __syncthreads();

        float4 acc = make_float4(0.f, 0.f, 0.f, 0.f);
        const float* pr = &psh[qrow * 257];
#pragma unroll 4
        for (int k = 0; k < NK_; k++) {
            const float p = pr[k];
            const float4 vv = *(const float4*)&kvsh[k * 68 + dd4];
            acc.x = fmaf(p, vv.x, acc.x);
            acc.y = fmaf(p, vv.y, acc.y);
            acc.z = fmaf(p, vv.z, acc.z);
            acc.w = fmaf(p, vv.w, acc.w);
        }
        *(float4*)&g_U[((size_t)(b * NQ_ + q0 + qrow)) * D_ + o * DK_ + dd4] = acc;
    }

    __syncthreads();
    if (tid < 8) atomicAdd(&g_ssq[b * NH_ + tid], ssb[tid]);
}

// ---------------- launcher ----------------
extern "C" void kernel_launch(void* const* d_in, const int* in_sizes, int n_in,
                              void* d_out, int out_size)
{
    const float* queries = (const float*)d_in[0];
    const float* Wq = (const float*)d_in[1];
    const float* bq = (const float*)d_in[2];
    const float* Wk = (const float*)d_in[3];
    const float* bk = (const float*)d_in[4];
    const float* Wv = (const float*)d_in[5];
    const float* bv = (const float*)d_in[6];
    const float* Wo = (const float*)d_in[7];
    const float* bo = (const float*)d_in[8];
    const float* srw = (const float*)d_in[9];
    const float* srb = (const float*)d_in[10];
    const float* lng = (const float*)d_in[11];
    const float* lnb = (const float*)d_in[12];
    const float* tw = (const float*)d_in[13];
    const float* tb = (const float*)d_in[14];
    float* out = (float*)d_out;

    float *qp, *x, *kp, *vp, *U;
    cudaGetSymbolAddress((void**)&qp, g_qp);
    cudaGetSymbolAddress((void**)&x,  g_x);
    cudaGetSymbolAddress((void**)&kp, g_kp);
    cudaGetSymbolAddress((void**)&vp, g_vp);
    cudaGetSymbolAddress((void**)&U,  g_U);

    const int attn_smem = (1024 + 17408 + 4112) * 4;  // 90176 B
    cudaFuncSetAttribute(attn_kernel, cudaFuncAttributeMaxDynamicSharedMemorySize, attn_smem);

    // 1) Q projection
    sgemm_bias<<<dim3(4, (B_ * NQ_) / 128), 256>>>(queries, Wq, bq, qp);
    // 2) spatial reduction conv + LayerNorm
    conv_ln_kernel<<<B_ * NK_, 512>>>(queries, srw, srb, lng, lnb);
    // 3) K, V projections
    sgemm_bias<<<dim3(4, (B_ * NK_) / 128), 256>>>(x, Wk, bk, kp);
    sgemm_bias<<<dim3(4, (B_ * NK_) / 128), 256>>>(x, Wv, bv, vp);
    // 4) V column sums + clear ssq (graph-replay safe)
    vcol_kernel<<<B_ * NH_, DK_>>>();
    // 5) fused attention (finalizes g_ssq, writes raw U)
    attn_kernel<<<dim3(NQ_ / 16, B_), 256, attn_smem>>>(tw, tb);
    // 6) per-batch corrected output bias (needs final g_ssq + g_vcol)
    obias_kernel<<<B_, 512>>>(Wo, bo);
    // 7) output projection with fused instance-norm scale -> d_out
    sgemm_o_fused<<<dim3(4, (B_ * NQ_) / 128), 256>>>(U, Wo, out);
}

// round 17
// speedup vs baseline: 1.2703x; 1.2703x over previous
#include <cuda_runtime.h>
#include <cuda_bf16.h>
#include <cstdint>

#define B_   16
#define NQ_  2304
#define D_   512
#define NH_  8
#define DK_  64
#define NK_  256
#define EPS_ 1e-5f

// ---------------- scratch (device globals; no allocation allowed) ----------------
__device__ float g_qp[(size_t)B_ * NQ_ * D_];   // Q projection
__device__ float g_x [(size_t)B_ * NK_ * D_];   // conv+LN output
__device__ float g_kp[(size_t)B_ * NK_ * D_];   // K projection
__device__ float g_vp[(size_t)B_ * NK_ * D_];   // V projection
__device__ float g_U [(size_t)B_ * NQ_ * D_];   // P@V (raw, pre-norm)
__device__ float g_vcol[B_ * D_];               // per-(b) V column sums (h-major)
__device__ float g_ssq [B_ * NH_];              // per-(b,h) sum of (P - 1/256)^2
__device__ __nv_bfloat16 g_wth[4][512 * 512];   // W^T hi  (Wt[n][k])
__device__ __nv_bfloat16 g_wtl[4][512 * 512];   // W^T lo

// ================= warp-MMA helpers (base sm_103 target: NO 'a'-suffix features) ======
__device__ __forceinline__ uint32_t smem_u32(const void* p) {
    uint32_t a;
    asm("{ .reg .u64 t; cvta.to.shared.u64 t, %1; cvt.u32.u64 %0, t; }" : "=r"(a) : "l"(p));
    return a;
}
__device__ __forceinline__ void ldm_x4(uint32_t& r0, uint32_t& r1, uint32_t& r2, uint32_t& r3,
                                       uint32_t addr) {
    asm volatile("ldmatrix.sync.aligned.m8n8.x4.shared.b16 {%0,%1,%2,%3}, [%4];"
                 : "=r"(r0), "=r"(r1), "=r"(r2), "=r"(r3) : "r"(addr));
}
__device__ __forceinline__ void ldm_x2(uint32_t& r0, uint32_t& r1, uint32_t addr) {
    asm volatile("ldmatrix.sync.aligned.m8n8.x2.shared.b16 {%0,%1}, [%2];"
                 : "=r"(r0), "=r"(r1) : "r"(addr));
}
__device__ __forceinline__ void mma16816(float* d, const uint32_t* a, uint32_t b0, uint32_t b1) {
    asm volatile("mma.sync.aligned.m16n8k16.row.col.f32.bf16.bf16.f32 "
                 "{%0,%1,%2,%3}, {%4,%5,%6,%7}, {%8,%9}, {%0,%1,%2,%3};"
                 : "+f"(d[0]), "+f"(d[1]), "+f"(d[2]), "+f"(d[3])
                 : "r"(a[0]), "r"(a[1]), "r"(a[2]), "r"(a[3]), "r"(b0), "r"(b1));
}

// ---------------- W transpose + split: Wt[n][k] = bf16split(W[k][n]) ----------------
__global__ __launch_bounds__(1024) void wt_split_kernel(const float* __restrict__ W0,
                                                        const float* __restrict__ W1,
                                                        const float* __restrict__ W2,
                                                        const float* __restrict__ W3)
{
    __shared__ float t[32][33];
    const int sel = blockIdx.z;
    const float* W = (sel == 0) ? W0 : (sel == 1) ? W1 : (sel == 2) ? W2 : W3;
    const int n0 = blockIdx.x * 32, k0 = blockIdx.y * 32;
    const int tx = threadIdx.x, ty = threadIdx.y;
    t[ty][tx] = W[(size_t)(k0 + ty) * 512 + n0 + tx];
    __syncthreads();
    const float v = t[tx][ty];                       // W[k0+tx][n0+ty]
    const __nv_bfloat16 h = __float2bfloat16(v);
    const __nv_bfloat16 l = __float2bfloat16(v - __bfloat162float(h));
    g_wth[sel][(size_t)(n0 + ty) * 512 + k0 + tx] = h;
    g_wtl[sel][(size_t)(n0 + ty) * 512 + k0 + tx] = l;
}

// ---------------- mma.sync split-bf16 GEMM: C[M,512] = A'[M,512] @ W + bias -----------
// 128x128 CTA tile, 8 warps of 32x64, m16n8k16, BK=32 chunks, 3 MMAs per tile (split).
// ssq_all != null (O-proj): A' = (A - vcol[b,c]/256) * rsqrt(ssq[b,h]/(NQ*NK)+eps),
// centered in fp32 BEFORE the bf16 split (avoids catastrophic cancellation).
#define PAD_ 40   // smem row pitch in bf16 (80 B: conflict-free ldmatrix)

__global__ __launch_bounds__(256) void mma_gemm(const float* __restrict__ A,
                                                const __nv_bfloat16* __restrict__ Bh,
                                                const __nv_bfloat16* __restrict__ Bl,
                                                const float* __restrict__ bias,
                                                const float* __restrict__ ssq_all,
                                                const float* __restrict__ vcol_all,
                                                float* __restrict__ C)
{
    __shared__ __nv_bfloat16 sAh[128][PAD_], sAl[128][PAD_];
    __shared__ __nv_bfloat16 sBh[128][PAD_], sBl[128][PAD_];

    const int tid  = threadIdx.x;
    const int wid  = tid >> 5;
    const int lane = tid & 31;
    const int bm = blockIdx.y * 128;
    const int bn = blockIdx.x * 128;
    const int b  = bm / NQ_;
    const int wm = (wid >> 1) * 32;    // warp M offset (4 warps along M)
    const int wn = (wid & 1) * 64;     // warp N offset (2 warps along N)

    const uint32_t sAh0 = smem_u32(&sAh[0][0]);
    const uint32_t sAl0 = smem_u32(&sAl[0][0]);
    const uint32_t sBh0 = smem_u32(&sBh[0][0]);
    const uint32_t sBl0 = smem_u32(&sBl[0][0]);

    float acc[2][8][4];
#pragma unroll
    for (int mi = 0; mi < 2; mi++)
#pragma unroll
        for (int j = 0; j < 8; j++)
#pragma unroll
            for (int e = 0; e < 4; e++) acc[mi][j][e] = 0.f;

    const int lrow = tid >> 1;          // loader row 0..127
    const int lseg = (tid & 1) * 16;    // loader k-segment 0 or 16

    for (int chunk = 0; chunk < 16; chunk++) {
        const int k0 = chunk * 32;
        const float s = ssq_all
            ? rsqrtf(ssq_all[b * NH_ + (k0 >> 6)] * (1.f / ((float)NQ_ * (float)NK_)) + EPS_)
            : 1.f;
        // ---- A chunk: fp32 -> (center, scale) -> hi/lo bf16 ----
        {
            const float* ar = &A[(size_t)(bm + lrow) * 512 + k0 + lseg];
            float v[16];
#pragma unroll
            for (int q = 0; q < 4; q++)
                *(float4*)&v[q * 4] = *(const float4*)&ar[q * 4];
            if (vcol_all) {
                const float* cr = &vcol_all[b * D_ + k0 + lseg];
#pragma unroll
                for (int e = 0; e < 16; e++)
                    v[e] = (v[e] - cr[e] * (1.f / 256.f)) * s;
            }
            __nv_bfloat162 hh[8], ll[8];
#pragma unroll
            for (int e = 0; e < 8; e++) {
                __nv_bfloat16 h0 = __float2bfloat16(v[2 * e]);
                __nv_bfloat16 h1 = __float2bfloat16(v[2 * e + 1]);
                __nv_bfloat16 l0 = __float2bfloat16(v[2 * e]     - __bfloat162float(h0));
                __nv_bfloat16 l1 = __float2bfloat16(v[2 * e + 1] - __bfloat162float(h1));
                hh[e] = __nv_bfloat162(h0, h1);
                ll[e] = __nv_bfloat162(l0, l1);
            }
            *(uint4*)&sAh[lrow][lseg]     = ((uint4*)hh)[0];
            *(uint4*)&sAh[lrow][lseg + 8] = ((uint4*)hh)[1];
            *(uint4*)&sAl[lrow][lseg]     = ((uint4*)ll)[0];
            *(uint4*)&sAl[lrow][lseg + 8] = ((uint4*)ll)[1];
        }
        // ---- B chunk (bf16 hi/lo from g_wth/g_wtl) ----
        {
            const __nv_bfloat16* bhr = &Bh[(size_t)(bn + lrow) * 512 + k0 + lseg];
            const __nv_bfloat16* blr = &Bl[(size_t)(bn + lrow) * 512 + k0 + lseg];
            *(uint4*)&sBh[lrow][lseg]     = ((const uint4*)bhr)[0];
            *(uint4*)&sBh[lrow][lseg + 8] = ((const uint4*)bhr)[1];
            *(uint4*)&sBl[lrow][lseg]     = ((const uint4*)blr)[0];
            *(uint4*)&sBl[lrow][lseg + 8] = ((const uint4*)blr)[1];
        }
        __syncthreads();

#pragma unroll
        for (int kk = 0; kk < 32; kk += 16) {
            uint32_t ah[2][4], al[2][4];
#pragma unroll
            for (int mi = 0; mi < 2; mi++) {
                const uint32_t aoff =
                    (uint32_t)(((wm + mi * 16 + (lane & 15)) * PAD_ + kk + ((lane >> 4) * 8)) * 2);
                ldm_x4(ah[mi][0], ah[mi][1], ah[mi][2], ah[mi][3], sAh0 + aoff);
                ldm_x4(al[mi][0], al[mi][1], al[mi][2], al[mi][3], sAl0 + aoff);
            }
#pragma unroll
            for (int j = 0; j < 8; j++) {
                const uint32_t boff =
                    (uint32_t)(((wn + j * 8 + (lane & 7)) * PAD_ + kk + (((lane >> 3) & 1) * 8)) * 2);
                uint32_t bh0, bh1, bl0, bl1;
                ldm_x2(bh0, bh1, sBh0 + boff);
                ldm_x2(bl0, bl1, sBl0 + boff);
#pragma unroll
                for (int mi = 0; mi < 2; mi++) {
                    mma16816(acc[mi][j], ah[mi], bh0, bh1);
                    mma16816(acc[mi][j], ah[mi], bl0, bl1);
                    mma16816(acc[mi][j], al[mi], bh0, bh1);
                }
            }
        }
        __syncthreads();
    }

    // ---- epilogue: d-frag -> C with bias ----
#pragma unroll
    for (int mi = 0; mi < 2; mi++) {
#pragma unroll
        for (int j = 0; j < 8; j++) {
            const int r0 = bm + wm + mi * 16 + (lane >> 2);
            const int c  = bn + wn + j * 8 + (lane & 3) * 2;
            float2 o0, o1;
            o0.x = acc[mi][j][0] + bias[c];
            o0.y = acc[mi][j][1] + bias[c + 1];
            o1.x = acc[mi][j][2] + bias[c];
            o1.y = acc[mi][j][3] + bias[c + 1];
            *(float2*)&C[(size_t)r0 * 512 + c]       = o0;
            *(float2*)&C[(size_t)(r0 + 8) * 512 + c] = o1;
        }
    }
}

// ---------------- depthwise 4x4 stride-3 pad-1 conv + LayerNorm(channel) ----------------
__global__ __launch_bounds__(512) void conv_ln_kernel(const float* __restrict__ q,
                                                      const float* __restrict__ srw,
                                                      const float* __restrict__ srb,
                                                      const float* __restrict__ lng,
                                                      const float* __restrict__ lnb)
{
    const int b   = blockIdx.x >> 8;
    const int pix = blockIdx.x & 255;
    const int oh  = pix >> 4, ow = pix & 15;
    const int c   = threadIdx.x;

    float acc = srb[c];
#pragma unroll
    for (int kh = 0; kh < 4; kh++) {
        int ih = oh * 3 - 1 + kh;
        if (ih < 0 || ih >= 48) continue;
#pragma unroll
        for (int kw = 0; kw < 4; kw++) {
            int iw = ow * 3 - 1 + kw;
            if (iw < 0 || iw >= 48) continue;
            acc = fmaf(q[((size_t)b * NQ_ + ih * 48 + iw) * D_ + c],
                       srw[c * 16 + kh * 4 + kw], acc);
        }
    }
    __shared__ float wred[16];
    __shared__ float stat;
    const int lane = c & 31, wid = c >> 5;

    float s = acc;
#pragma unroll
    for (int off = 16; off; off >>= 1) s += __shfl_xor_sync(0xffffffffu, s, off);
    if (lane == 0) wred[wid] = s;
    __syncthreads();
    if (c == 0) {
        float t = 0.f;
#pragma unroll
        for (int i = 0; i < 16; i++) t += wred[i];
        stat = t * (1.f / 512.f);
    }
    __syncthreads();
    const float mu = stat;
    const float dv = acc - mu;
    float s2 = dv * dv;
#pragma unroll
    for (int off = 16; off; off >>= 1) s2 += __shfl_xor_sync(0xffffffffu, s2, off);
    __syncthreads();
    if (lane == 0) wred[wid] = s2;
    __syncthreads();
    if (c == 0) {
        float t = 0.f;
#pragma unroll
        for (int i = 0; i < 16; i++) t += wred[i];
        stat = t * (1.f / 512.f);
    }
    __syncthreads();
    const float var = stat;
    g_x[((size_t)b * NK_ + pix) * D_ + c] = dv * rsqrtf(var + EPS_) * lng[c] + lnb[c];
}

// ---------------- V column sums + clear ssq ----------------
__global__ void vcol_kernel()
{
    const int bh = blockIdx.x;
    const int b = bh >> 3, h = bh & 7;
    const int d = threadIdx.x;
    float s = 0.f;
    for (int n = 0; n < NK_; n++)
        s += g_vp[((size_t)b * NK_ + n) * D_ + h * DK_ + d];
    g_vcol[b * D_ + h * DK_ + d] = s;
    if (d == 0) g_ssq[bh] = 0.f;
}

// ---------------- fused attention: scores -> head-mix -> softmax -> ssq -> U = P@V ----------
__global__ __launch_bounds__(256, 1) void attn_kernel(const float* __restrict__ tw,
                                                      const float* __restrict__ tb)
{
    extern __shared__ float smf[];
    float* qsh  = smf;
    float* kvsh = smf + 1024;
    float* psh  = smf + 1024 + 17408;
    __shared__ float twsh[64];
    __shared__ float tbsh[8];
    __shared__ float ssb[8];

    const int tid  = threadIdx.x;
    const int w    = tid >> 5;
    const int lane = tid & 31;
    const int b    = blockIdx.y;
    const int q0   = blockIdx.x * 16;

    if (tid < 64) twsh[tid] = tw[tid];
    if (tid < 8) { tbsh[tid] = tb[tid]; ssb[tid] = 0.f; }

    float macc[8][2][8];
#pragma unroll
    for (int o = 0; o < 8; o++)
#pragma unroll
        for (int qq = 0; qq < 2; qq++)
#pragma unroll
            for (int kk = 0; kk < 8; kk++) macc[o][qq][kk] = 0.f;

    for (int i = 0; i < 8; i++) {
        {
            int j = tid;
            int r = j >> 4, d4 = (j & 15) * 4;
            *(float4*)&qsh[r * 64 + d4] =
                *(const float4*)&g_qp[((size_t)(b * NQ_ + q0 + r)) * D_ + i * DK_ + d4];
        }
        for (int j = tid; j < 4096; j += 256) {
            int k = j >> 4, d4 = (j & 15) * 4;
            const float4 kv = *(const float4*)&g_kp[((size_t)(b * NK_ + k)) * D_ + i * DK_ + d4];
            kvsh[(d4 + 0) * 257 + k] = kv.x;
            kvsh[(d4 + 1) * 257 + k] = kv.y;
            kvsh[(d4 + 2) * 257 + k] = kv.z;
            kvsh[(d4 + 3) * 257 + k] = kv.w;
        }
        __syncthreads();

        float sacc[2][8];
#pragma unroll
        for (int qq = 0; qq < 2; qq++)
#pragma unroll
            for (int kk = 0; kk < 8; kk++) sacc[qq][kk] = 0.f;

#pragma unroll 8
        for (int d = 0; d < 64; d++) {
            const float q0v = qsh[(2 * w) * 64 + d];
            const float q1v = qsh[(2 * w + 1) * 64 + d];
            const float* kr = &kvsh[d * 257 + lane];
#pragma unroll
            for (int kk = 0; kk < 8; kk++) {
                const float kv = kr[kk * 32];
                sacc[0][kk] = fmaf(q0v, kv, sacc[0][kk]);
                sacc[1][kk] = fmaf(q1v, kv, sacc[1][kk]);
            }
        }
#pragma unroll
        for (int o = 0; o < 8; o++) {
            const float wv = twsh[o * 8 + i] * 0.125f;
#pragma unroll
            for (int qq = 0; qq < 2; qq++)
#pragma unroll
                for (int kk = 0; kk < 8; kk++)
                    macc[o][qq][kk] = fmaf(wv, sacc[qq][kk], macc[o][qq][kk]);
        }
        __syncthreads();
    }

#pragma unroll
    for (int o = 0; o < 8; o++) {
        float ssq_o = 0.f;
        const float bias = tbsh[o];
#pragma unroll
        for (int qq = 0; qq < 2; qq++) {
            float mx = -1e30f;
#pragma unroll
            for (int kk = 0; kk < 8; kk++) {
                macc[o][qq][kk] += bias;
                mx = fmaxf(mx, macc[o][qq][kk]);
            }
#pragma unroll
            for (int off = 16; off; off >>= 1)
                mx = fmaxf(mx, __shfl_xor_sync(0xffffffffu, mx, off));
            float s = 0.f;
#pragma unroll
            for (int kk = 0; kk < 8; kk++) {
                float e = __expf(macc[o][qq][kk] - mx);
                macc[o][qq][kk] = e;
                s += e;
            }
#pragma unroll
            for (int off = 16; off; off >>= 1)
                s += __shfl_xor_sync(0xffffffffu, s, off);
            const float inv = 1.f / s;
#pragma unroll
            for (int kk = 0; kk < 8; kk++) {
                const float p = macc[o][qq][kk] * inv;
                macc[o][qq][kk] = p;
                const float d = p - (1.f / 256.f);
                ssq_o = fmaf(d, d, ssq_o);
            }
        }
#pragma unroll
        for (int off = 16; off; off >>= 1)
            ssq_o += __shfl_xor_sync(0xffffffffu, ssq_o, off);
        if (lane == 0) atomicAdd(&ssb[o], ssq_o);
    }

    const int qh = w & 1, dq = w >> 1;
    const int ql = lane >> 2, dl = lane & 3;
    const int qrow = qh * 8 + ql;
    const int dd4  = dq * 16 + dl * 4;

#pragma unroll
    for (int o = 0; o < 8; o++) {
        __syncthreads();
#pragma unroll
        for (int qq = 0; qq < 2; qq++)
#pragma unroll
            for (int kk = 0; kk < 8; kk++)
                psh[(2 * w + qq) * 257 + lane + 32 * kk] = macc[o][qq][kk];
        for (int j = tid; j < 4096; j += 256) {
            int k = j >> 4, d4 = (j & 15) * 4;
            *(float4*)&kvsh[k * 68 + d4] =
                *(const float4*)&g_vp[((size_t)(b * NK_ + k)) * D_ + o * DK_ + d4];
        }
        __syncthreads();

        float4 acc = make_float4(0.f, 0.f, 0.f, 0.f);
        const float* pr = &psh[qrow * 257];
#pragma unroll 4
        for (int k = 0; k < NK_; k++) {
            const float p = pr[k];
            const float4 vv = *(const float4*)&kvsh[k * 68 + dd4];
            acc.x = fmaf(p, vv.x, acc.x);
            acc.y = fmaf(p, vv.y, acc.y);
            acc.z = fmaf(p, vv.z, acc.z);
            acc.w = fmaf(p, vv.w, acc.w);
        }
        *(float4*)&g_U[((size_t)(b * NQ_ + q0 + qrow)) * D_ + o * DK_ + dd4] = acc;
    }

    __syncthreads();
    if (tid < 8) atomicAdd(&g_ssq[b * NH_ + tid], ssb[tid]);
}

// ---------------- launcher ----------------
extern "C" void kernel_launch(void* const* d_in, const int* in_sizes, int n_in,
                              void* d_out, int out_size)
{
    const float* queries = (const float*)d_in[0];
    const float* Wq = (const float*)d_in[1];
    const float* bq = (const float*)d_in[2];
    const float* Wk = (const float*)d_in[3];
    const float* bk = (const float*)d_in[4];
    const float* Wv = (const float*)d_in[5];
    const float* bv = (const float*)d_in[6];
    const float* Wo = (const float*)d_in[7];
    const float* bo = (const float*)d_in[8];
    const float* srw = (const float*)d_in[9];
    const float* srb = (const float*)d_in[10];
    const float* lng = (const float*)d_in[11];
    const float* lnb = (const float*)d_in[12];
    const float* tw = (const float*)d_in[13];
    const float* tb = (const float*)d_in[14];
    float* out = (float*)d_out;

    float *qp, *x, *kp, *vp, *U, *vcol, *ssq;
    __nv_bfloat16 *wth, *wtl;
    cudaGetSymbolAddress((void**)&qp, g_qp);
    cudaGetSymbolAddress((void**)&x,  g_x);
    cudaGetSymbolAddress((void**)&kp, g_kp);
    cudaGetSymbolAddress((void**)&vp, g_vp);
    cudaGetSymbolAddress((void**)&U,  g_U);
    cudaGetSymbolAddress((void**)&vcol, g_vcol);
    cudaGetSymbolAddress((void**)&ssq, g_ssq);
    cudaGetSymbolAddress((void**)&wth, g_wth);
    cudaGetSymbolAddress((void**)&wtl, g_wtl);

    const int attn_smem = (1024 + 17408 + 4112) * 4;  // 90176 B
    cudaFuncSetAttribute(attn_kernel, cudaFuncAttributeMaxDynamicSharedMemorySize, attn_smem);

    const size_t WSZ = 512 * 512;

    // 0) weight transpose + split (Wq, Wk, Wv, Wo)
    wt_split_kernel<<<dim3(16, 16, 4), dim3(32, 32)>>>(Wq, Wk, Wv, Wo);
    // 1) Q projection (HMMA tensor cores, split-bf16)
    mma_gemm<<<dim3(4, (B_ * NQ_) / 128), 256>>>(
        queries, wth + 0 * WSZ, wtl + 0 * WSZ, bq, nullptr, nullptr, qp);
    // 2) spatial reduction conv + LayerNorm
    conv_ln_kernel<<<B_ * NK_, 512>>>(queries, srw, srb, lng, lnb);
    // 3) K, V projections
    mma_gemm<<<dim3(4, (B_ * NK_) / 128), 256>>>(
        x, wth + 1 * WSZ, wtl + 1 * WSZ, bk, nullptr, nullptr, kp);
    mma_gemm<<<dim3(4, (B_ * NK_) / 128), 256>>>(
        x, wth + 2 * WSZ, wtl + 2 * WSZ, bv, nullptr, nullptr, vp);
    // 4) V column sums + clear ssq
    vcol_kernel<<<B_ * NH_, DK_>>>();
    // 5) fused attention (finalizes g_ssq, writes raw U)
    attn_kernel<<<dim3(NQ_ / 16, B_), 256, attn_smem>>>(tw, tb);
    // 6) output projection: A centered/scaled in fp32 before split -> d_out
    mma_gemm<<<dim3(4, (B_ * NQ_) / 128), 256>>>(
        U, wth + 3 * WSZ, wtl + 3 * WSZ, bo, ssq, vcol, out);
}